// round 2
// baseline (speedup 1.0000x reference)
#include <cuda_runtime.h>
#include <cuda_bf16.h>
#include <mma.h>

using namespace nvcuda;

#define T_    128
#define B_    256
#define D_    1024
#define H_    1024
#define V_    32000
#define TAGS_ 1024
#define GQ    32      // 4 gates * 8 qubits

// ---------------- scratch (static device globals; no cudaMalloc allowed) ----
__device__ float          g_embproj[V_ * GQ];          // emb @ Wg_x  (4.1 MB)
__device__ __nv_bfloat16  g_lstm[(size_t)T_ * B_ * H_]; // lstm_out bf16 (64 MB)
__device__ __nv_bfloat16  g_wtag[H_ * TAGS_];          // W_tag bf16 (2 MB)

// ---------------- K0: W_tag -> bf16 -----------------------------------------
__global__ void wtag_convert(const float* __restrict__ w) {
    int i = blockIdx.x * 256 + threadIdx.x;
    g_wtag[i] = __float2bfloat16(w[i]);
}

// ---------------- K1: embproj = emb @ Wg[:, :D, :]  (32000 x 32) ------------
__global__ __launch_bounds__(256) void embproj_kernel(const float* __restrict__ emb,
                                                      const float* __restrict__ Wg) {
    __shared__ float As[128][33];
    __shared__ __align__(16) float Bs[32][36];
    int tid = threadIdx.x;
    int v0  = blockIdx.x * 128;
    int tr  = tid >> 3;       // 0..31 -> rows tr*4..tr*4+3
    int tc  = tid & 7;        // 0..7  -> cols tc*4..tc*4+3
    float acc[4][4] = {};

    for (int k0 = 0; k0 < D_; k0 += 32) {
        // load A tile 128x32 (float4 per thread x4)
        #pragma unroll
        for (int i = 0; i < 4; i++) {
            int f4  = tid + i * 256;       // float4 index, 1024 total
            int row = f4 >> 3;
            int c4  = (f4 & 7) * 4;
            float4 a = *(const float4*)&emb[(size_t)(v0 + row) * D_ + k0 + c4];
            As[row][c4 + 0] = a.x; As[row][c4 + 1] = a.y;
            As[row][c4 + 2] = a.z; As[row][c4 + 3] = a.w;
        }
        // load B tile 32x32: Bs[k][gq] = Wg[g][k0+k][q]
        #pragma unroll
        for (int i = 0; i < 4; i++) {
            int idx = tid + i * 256;
            int k = idx >> 5, gq = idx & 31;
            int g = gq >> 3,  q  = gq & 7;
            Bs[k][gq] = Wg[g * (2048 * 8) + (k0 + k) * 8 + q];
        }
        __syncthreads();
        #pragma unroll
        for (int k = 0; k < 32; k++) {
            float4 b4 = *(const float4*)&Bs[k][tc * 4];
            #pragma unroll
            for (int i = 0; i < 4; i++) {
                float a = As[tr * 4 + i][k];
                acc[i][0] += a * b4.x; acc[i][1] += a * b4.y;
                acc[i][2] += a * b4.z; acc[i][3] += a * b4.w;
            }
        }
        __syncthreads();
    }
    #pragma unroll
    for (int i = 0; i < 4; i++) {
        float4 o = make_float4(acc[i][0], acc[i][1], acc[i][2], acc[i][3]);
        *(float4*)&g_embproj[(v0 + tr * 4 + i) * GQ + tc * 4] = o;
    }
}

// ---------------- K2: LSTM recurrence, one block per batch element ----------
// smem: WghT[32][1024] fp32 (128K) | h[1024] | xq[128][32] | qcos[32]
#define LSTM_SMEM ((32 * 1024 + 1024 + 128 * 32 + 32) * 4)

__global__ __launch_bounds__(1024, 1) void lstm_kernel(
    const int*   __restrict__ sentence,
    const float* __restrict__ Wg,
    const float* __restrict__ bg,
    const float* __restrict__ theta,
    const float* __restrict__ Wp,
    const float* __restrict__ bp) {
    extern __shared__ float sm[];
    float* WghT = sm;                 // 32*1024
    float* h_sm = sm + 32 * 1024;     // 1024
    float* xq   = h_sm + 1024;        // 128*32
    float* qcos = xq + 128 * 32;      // 32

    const int tid  = threadIdx.x;     // hidden unit j
    const int b    = blockIdx.x;
    const int w    = tid >> 5;        // warp -> (g,q) index 0..31
    const int lane = tid & 31;

    // load transposed Wg_h: WghT[gq][j] = Wg[g][D + j][q]
    #pragma unroll
    for (int it = 0; it < 4; it++) {
        int p  = tid + it * 1024;     // (g, j2) pair, 4096 total
        int g  = p >> 10, j2 = p & 1023;
        const float* src = Wg + g * (2048 * 8) + (1024 + j2) * 8;
        float4 v0 = *(const float4*)src;
        float4 v1 = *(const float4*)(src + 4);
        WghT[(g * 8 + 0) * 1024 + j2] = v0.x;
        WghT[(g * 8 + 1) * 1024 + j2] = v0.y;
        WghT[(g * 8 + 2) * 1024 + j2] = v0.z;
        WghT[(g * 8 + 3) * 1024 + j2] = v0.w;
        WghT[(g * 8 + 4) * 1024 + j2] = v1.x;
        WghT[(g * 8 + 5) * 1024 + j2] = v1.y;
        WghT[(g * 8 + 6) * 1024 + j2] = v1.z;
        WghT[(g * 8 + 7) * 1024 + j2] = v1.w;
    }
    // xq[t][gq] = embproj[token][gq] + bg[gq] + theta[gq]
    #pragma unroll
    for (int it = 0; it < 4; it++) {
        int p = tid + it * 1024;
        int t = p >> 5, gq = p & 31;
        int token = sentence[t * B_ + b];
        xq[t * GQ + gq] = g_embproj[token * GQ + gq] + bg[gq] + theta[gq];
    }
    // per-thread Wp slice and bias
    float wpreg[32];
    #pragma unroll
    for (int gq = 0; gq < 32; gq++) wpreg[gq] = Wp[gq * H_ + tid];
    float bp4[4];
    #pragma unroll
    for (int g = 0; g < 4; g++) bp4[g] = bp[g * H_ + tid];

    h_sm[tid] = 0.f;
    float c = 0.f;
    __syncthreads();

    for (int t = 0; t < T_; t++) {
        // hpart matvec: warp w computes dot(h, WghT[w])
        const float4* hv = (const float4*)h_sm;
        const float4* wv = (const float4*)(WghT + w * 1024);
        float s = 0.f;
        #pragma unroll
        for (int k = 0; k < 8; k++) {
            float4 hh = hv[lane + k * 32];
            float4 ww = wv[lane + k * 32];
            s += hh.x * ww.x + hh.y * ww.y + hh.z * ww.z + hh.w * ww.w;
        }
        #pragma unroll
        for (int off = 16; off > 0; off >>= 1)
            s += __shfl_xor_sync(0xffffffffu, s, off);
        if (lane == 0) qcos[w] = __cosf(s + xq[t * GQ + w]);
        __syncthreads();

        // gates: proj[g] = bp + sum_q qcos[g*8+q] * Wp[g,q,j]
        const float4* qc4 = (const float4*)qcos;
        float pj[4];
        #pragma unroll
        for (int g = 0; g < 4; g++) {
            float4 qa = qc4[2 * g];
            float4 qb = qc4[2 * g + 1];
            float a = bp4[g];
            a += qa.x * wpreg[g * 8 + 0]; a += qa.y * wpreg[g * 8 + 1];
            a += qa.z * wpreg[g * 8 + 2]; a += qa.w * wpreg[g * 8 + 3];
            a += qb.x * wpreg[g * 8 + 4]; a += qb.y * wpreg[g * 8 + 5];
            a += qb.z * wpreg[g * 8 + 6]; a += qb.w * wpreg[g * 8 + 7];
            pj[g] = a;
        }
        float fg = __fdividef(1.f, 1.f + __expf(-pj[0]));
        float ig = __fdividef(1.f, 1.f + __expf(-pj[1]));
        float gg = __tanhf(pj[2]);
        float og = __fdividef(1.f, 1.f + __expf(-pj[3]));
        c = fg * c + ig * gg;
        float h = og * __tanhf(c);

        h_sm[tid] = h;
        g_lstm[((size_t)t * B_ + b) * H_ + tid] = __float2bfloat16(h);
        __syncthreads();
    }
}

// ---------------- K3: fused tag GEMM (bf16 WMMA) + log_softmax over batch ---
// block = one (t, 128-tag chunk): GEMM tile 256(b) x 128(tags), K = 1024.
// b_tag cancels in log_softmax over the batch axis -> omitted.
#define TAG_SMEM (256 * 136 * 4 + 512 * 4)   // epilogue tile dominates (aliases GEMM tiles)

__global__ __launch_bounds__(512, 1) void tag_kernel(float* __restrict__ out) {
    extern __shared__ char smraw[];
    __nv_bfloat16* Asm = (__nv_bfloat16*)smraw;    // 256 x 40 (ld=40)
    __nv_bfloat16* Bsm = Asm + 256 * 40;           // 32 x 136 (ld=136)
    float* Osm = (float*)smraw;                    // 256 x 136 fp32 (aliases A/B)
    float* red = Osm + 256 * 136;                  // 4 x 128 partials

    const int tid = threadIdx.x;
    const int t   = blockIdx.y;
    const int c0  = blockIdx.x * 128;
    const int w   = tid >> 5;
    const int wy  = w >> 2;        // 0..3 -> 64 rows
    const int wx  = w & 3;         // 0..3 -> 32 cols

    wmma::fragment<wmma::accumulator, 16, 16, 16, float> acc[4][2];
    #pragma unroll
    for (int i = 0; i < 4; i++)
        #pragma unroll
        for (int j = 0; j < 2; j++) wmma::fill_fragment(acc[i][j], 0.f);

    for (int k0 = 0; k0 < H_; k0 += 32) {
        // A: 256x32 bf16 (8192 elems = 512 thr x 2 x uint4)
        #pragma unroll
        for (int it = 0; it < 2; it++) {
            int e   = tid + it * 512;     // 8-elem group
            int row = e >> 2;
            int cg  = (e & 3) * 8;
            *(uint4*)&Asm[row * 40 + cg] =
                *(const uint4*)&g_lstm[((size_t)t * B_ + row) * H_ + k0 + cg];
        }
        // B: 32x128 bf16 (4096 elems = 512 thr x uint4)
        {
            int kr = tid >> 4;
            int cg = (tid & 15) * 8;
            *(uint4*)&Bsm[kr * 136 + cg] =
                *(const uint4*)&g_wtag[(size_t)(k0 + kr) * TAGS_ + c0 + cg];
        }
        __syncthreads();
        #pragma unroll
        for (int ks = 0; ks < 32; ks += 16) {
            wmma::fragment<wmma::matrix_a, 16, 16, 16, __nv_bfloat16, wmma::row_major> af[4];
            wmma::fragment<wmma::matrix_b, 16, 16, 16, __nv_bfloat16, wmma::row_major> bf[2];
            #pragma unroll
            for (int i = 0; i < 4; i++)
                wmma::load_matrix_sync(af[i], &Asm[(wy * 64 + i * 16) * 40 + ks], 40);
            #pragma unroll
            for (int j = 0; j < 2; j++)
                wmma::load_matrix_sync(bf[j], &Bsm[ks * 136 + wx * 32 + j * 16], 136);
            #pragma unroll
            for (int i = 0; i < 4; i++)
                #pragma unroll
                for (int j = 0; j < 2; j++)
                    wmma::mma_sync(acc[i][j], af[i], bf[j], acc[i][j]);
        }
        __syncthreads();
    }

    // spill accumulators to smem tile (safe: trailing sync above)
    #pragma unroll
    for (int i = 0; i < 4; i++)
        #pragma unroll
        for (int j = 0; j < 2; j++)
            wmma::store_matrix_sync(&Osm[(wy * 64 + i * 16) * 136 + wx * 32 + j * 16],
                                    acc[i][j], 136, wmma::mem_row_major);
    __syncthreads();

    // log_softmax over the 256 rows (batch) per column (tag)
    const int p = tid >> 7;      // 0..3, 64 rows each
    const int c = tid & 127;
    float m = -1e30f;
    #pragma unroll 8
    for (int i = 0; i < 64; i++) m = fmaxf(m, Osm[(p * 64 + i) * 136 + c]);
    red[p * 128 + c] = m;
    __syncthreads();
    float M = fmaxf(fmaxf(red[c], red[128 + c]), fmaxf(red[256 + c], red[384 + c]));
    float ssum = 0.f;
    #pragma unroll 8
    for (int i = 0; i < 64; i++) ssum += __expf(Osm[(p * 64 + i) * 136 + c] - M);
    __syncthreads();
    red[p * 128 + c] = ssum;
    __syncthreads();
    float lse = M + logf(red[c] + red[128 + c] + red[256 + c] + red[384 + c]);
    #pragma unroll 8
    for (int i = 0; i < 64; i++) {
        int b = p * 64 + i;
        out[((size_t)t * B_ + b) * TAGS_ + c0 + c] = Osm[b * 136 + c] - lse;
    }
}

// ---------------- launch -----------------------------------------------------
extern "C" void kernel_launch(void* const* d_in, const int* in_sizes, int n_in,
                              void* d_out, int out_size) {
    const int*   sentence = (const int*)  d_in[0];
    const float* emb      = (const float*)d_in[1];
    const float* Wg       = (const float*)d_in[2];
    const float* bg       = (const float*)d_in[3];
    const float* theta    = (const float*)d_in[4];
    const float* Wp       = (const float*)d_in[5];
    const float* bp       = (const float*)d_in[6];
    const float* W_tag    = (const float*)d_in[7];
    // d_in[8] = b_tag: cancels in log_softmax over batch axis -> unused
    float* out = (float*)d_out;

    cudaFuncSetAttribute(lstm_kernel, cudaFuncAttributeMaxDynamicSharedMemorySize, LSTM_SMEM);
    cudaFuncSetAttribute(tag_kernel,  cudaFuncAttributeMaxDynamicSharedMemorySize, TAG_SMEM);

    wtag_convert<<<(H_ * TAGS_) / 256, 256>>>(W_tag);
    embproj_kernel<<<V_ / 128, 256>>>(emb, Wg);
    lstm_kernel<<<B_, 1024, LSTM_SMEM>>>(sentence, Wg, bg, theta, Wp, bp);
    dim3 g3(TAGS_ / 128, T_);
    tag_kernel<<<g3, 512, TAG_SMEM>>>(out);
}

// round 3
// speedup vs baseline: 1.3505x; 1.3505x over previous
#include <cuda_runtime.h>
#include <cuda_bf16.h>
#include <mma.h>

using namespace nvcuda;

#define T_    128
#define B_    256
#define D_    1024
#define H_    1024
#define V_    32000
#define TAGS_ 1024
#define GQ    32      // 4 gates * 8 qubits

// ---------------- scratch (static device globals; no cudaMalloc allowed) ----
__device__ float          g_embproj[V_ * GQ];           // emb @ Wg_x  (4.1 MB)
__device__ __nv_bfloat16  g_lstm[(size_t)T_ * B_ * H_]; // lstm_out bf16 (64 MB)
__device__ __nv_bfloat16  g_wtag[H_ * TAGS_];           // W_tag bf16 (2 MB)

// ---------------- helpers ----------------------------------------------------
__device__ __forceinline__ void cp16(void* smem, const void* gmem) {
    unsigned sa = (unsigned)__cvta_generic_to_shared(smem);
    asm volatile("cp.async.cg.shared.global [%0], [%1], 16;\n" :: "r"(sa), "l"(gmem));
}
__device__ __forceinline__ float fast_sigmoid(float x) {
    return 0.5f + 0.5f * __tanhf(0.5f * x);
}

// ---------------- K0: W_tag -> bf16 -----------------------------------------
__global__ void wtag_convert(const float* __restrict__ w) {
    int i = blockIdx.x * 256 + threadIdx.x;
    g_wtag[i] = __float2bfloat16(w[i]);
}

// ---------------- K1: embproj = emb @ Wg[:, :D, :]  (32000 x 32) ------------
__global__ __launch_bounds__(256) void embproj_kernel(const float* __restrict__ emb,
                                                      const float* __restrict__ Wg) {
    __shared__ float As[128][33];
    __shared__ __align__(16) float Bs[32][36];
    int tid = threadIdx.x;
    int v0  = blockIdx.x * 128;
    int tr  = tid >> 3;
    int tc  = tid & 7;
    float acc[4][4] = {};

    for (int k0 = 0; k0 < D_; k0 += 32) {
        #pragma unroll
        for (int i = 0; i < 4; i++) {
            int f4  = tid + i * 256;
            int row = f4 >> 3;
            int c4  = (f4 & 7) * 4;
            float4 a = *(const float4*)&emb[(size_t)(v0 + row) * D_ + k0 + c4];
            As[row][c4 + 0] = a.x; As[row][c4 + 1] = a.y;
            As[row][c4 + 2] = a.z; As[row][c4 + 3] = a.w;
        }
        #pragma unroll
        for (int i = 0; i < 4; i++) {
            int idx = tid + i * 256;
            int k = idx >> 5, gq = idx & 31;
            int g = gq >> 3,  q  = gq & 7;
            Bs[k][gq] = Wg[g * (2048 * 8) + (k0 + k) * 8 + q];
        }
        __syncthreads();
        #pragma unroll
        for (int k = 0; k < 32; k++) {
            float4 b4 = *(const float4*)&Bs[k][tc * 4];
            #pragma unroll
            for (int i = 0; i < 4; i++) {
                float a = As[tr * 4 + i][k];
                acc[i][0] += a * b4.x; acc[i][1] += a * b4.y;
                acc[i][2] += a * b4.z; acc[i][3] += a * b4.w;
            }
        }
        __syncthreads();
    }
    #pragma unroll
    for (int i = 0; i < 4; i++) {
        float4 o = make_float4(acc[i][0], acc[i][1], acc[i][2], acc[i][3]);
        *(float4*)&g_embproj[(v0 + tr * 4 + i) * GQ + tc * 4] = o;
    }
}

// ---------------- K2: LSTM recurrence, one block per TWO batch elements -----
// smem floats: W2[1024][33] | xq0[128*32] | xq1 | qcos0[32] | qcos1[32]
//              | red0[32*33] | red1[32*33]
#define LSTM_SMEM ((1024 * 33 + 2 * 4096 + 2 * 32 + 2 * 32 * 33) * 4)

__global__ __launch_bounds__(1024, 1) void lstm_kernel(
    const int*   __restrict__ sentence,
    const float* __restrict__ Wg,
    const float* __restrict__ bg,
    const float* __restrict__ theta,
    const float* __restrict__ Wp,
    const float* __restrict__ bp) {
    extern __shared__ float sm[];
    float* W2    = sm;                      // 1024*33
    float* xq0   = sm + 1024 * 33;          // 4096
    float* xq1   = xq0 + 4096;              // 4096
    float* qcos0 = xq1 + 4096;              // 32 (16B aligned)
    float* qcos1 = qcos0 + 32;              // 32
    float* red0  = qcos1 + 32;              // 32*33
    float* red1  = red0 + 32 * 33;          // 32*33

    const int tid  = threadIdx.x;           // hidden unit j
    const int warp = tid >> 5;
    const int lane = tid & 31;
    const int b0   = blockIdx.x * 2;

    // transposed hidden weights: W2[j][gq] = Wg[g][D + j][q]
    #pragma unroll
    for (int it = 0; it < 4; it++) {
        int p = tid + it * 1024;
        int g = p >> 10, j = p & 1023;
        const float* src = Wg + g * (2048 * 8) + (1024 + j) * 8;
        float4 v0 = *(const float4*)src;
        float4 v1 = *(const float4*)(src + 4);
        float* dst = W2 + j * 33 + g * 8;
        dst[0] = v0.x; dst[1] = v0.y; dst[2] = v0.z; dst[3] = v0.w;
        dst[4] = v1.x; dst[5] = v1.y; dst[6] = v1.z; dst[7] = v1.w;
    }
    // xq[b][t][gq] = embproj[token][gq] + bg[gq] + theta[gq]
    #pragma unroll
    for (int it = 0; it < 8; it++) {
        int p  = tid + it * 1024;
        int bb = p >> 12;
        int r  = p & 4095;
        int t  = r >> 5, gq = r & 31;
        int token = sentence[t * B_ + b0 + bb];
        float v = g_embproj[token * GQ + gq] + bg[gq] + theta[gq];
        (bb ? xq1 : xq0)[t * 32 + gq] = v;
    }
    float wpreg[32];
    #pragma unroll
    for (int gq = 0; gq < 32; gq++) wpreg[gq] = Wp[gq * H_ + tid];
    float bp4[4];
    #pragma unroll
    for (int g = 0; g < 4; g++) bp4[g] = bp[g * H_ + tid];

    float h0 = 0.f, h1 = 0.f, c0 = 0.f, c1 = 0.f;
    __syncthreads();

    for (int t = 0; t < T_; t++) {
        // matvec: warp w covers j in [32w, 32w+32), lane = gq. h lives in regs.
        float s0 = 0.f, s1 = 0.f;
        const float* wrow = W2 + (warp * 32) * 33 + lane;
        #pragma unroll
        for (int j = 0; j < 32; j++) {
            float wv = wrow[j * 33];
            s0 = fmaf(__shfl_sync(0xffffffffu, h0, j), wv, s0);
            s1 = fmaf(__shfl_sync(0xffffffffu, h1, j), wv, s1);
        }
        red0[warp * 33 + lane] = s0;
        red1[warp * 33 + lane] = s1;
        __syncthreads();
        if (warp < 2) {
            const float* rd = warp ? red1 : red0;
            float tt = 0.f;
            #pragma unroll
            for (int wi = 0; wi < 32; wi++) tt += rd[wi * 33 + lane];
            float x = (warp ? xq1 : xq0)[t * 32 + lane];
            (warp ? qcos1 : qcos0)[lane] = __cosf(tt + x);
        }
        __syncthreads();

        // gates for both batch elements
        const float4* qa0 = (const float4*)qcos0;
        const float4* qa1 = (const float4*)qcos1;
        float pj0[4], pj1[4];
        #pragma unroll
        for (int g = 0; g < 4; g++) {
            float4 xa = qa0[2 * g], ya = qa0[2 * g + 1];
            float a = bp4[g];
            a = fmaf(xa.x, wpreg[g * 8 + 0], a); a = fmaf(xa.y, wpreg[g * 8 + 1], a);
            a = fmaf(xa.z, wpreg[g * 8 + 2], a); a = fmaf(xa.w, wpreg[g * 8 + 3], a);
            a = fmaf(ya.x, wpreg[g * 8 + 4], a); a = fmaf(ya.y, wpreg[g * 8 + 5], a);
            a = fmaf(ya.z, wpreg[g * 8 + 6], a); a = fmaf(ya.w, wpreg[g * 8 + 7], a);
            pj0[g] = a;
            float4 xb = qa1[2 * g], yb = qa1[2 * g + 1];
            float b = bp4[g];
            b = fmaf(xb.x, wpreg[g * 8 + 0], b); b = fmaf(xb.y, wpreg[g * 8 + 1], b);
            b = fmaf(xb.z, wpreg[g * 8 + 2], b); b = fmaf(xb.w, wpreg[g * 8 + 3], b);
            b = fmaf(yb.x, wpreg[g * 8 + 4], b); b = fmaf(yb.y, wpreg[g * 8 + 5], b);
            b = fmaf(yb.z, wpreg[g * 8 + 6], b); b = fmaf(yb.w, wpreg[g * 8 + 7], b);
            pj1[g] = b;
        }
        float fg = fast_sigmoid(pj0[0]);
        float ig = fast_sigmoid(pj0[1]);
        float gg = __tanhf(pj0[2]);
        float og = fast_sigmoid(pj0[3]);
        c0 = fg * c0 + ig * gg;
        h0 = og * __tanhf(c0);

        fg = fast_sigmoid(pj1[0]);
        ig = fast_sigmoid(pj1[1]);
        gg = __tanhf(pj1[2]);
        og = fast_sigmoid(pj1[3]);
        c1 = fg * c1 + ig * gg;
        h1 = og * __tanhf(c1);

        size_t base = ((size_t)t * B_ + b0) * H_ + tid;
        g_lstm[base]      = __float2bfloat16(h0);
        g_lstm[base + H_] = __float2bfloat16(h1);
    }
}

// ---------------- K3: fused tag GEMM (bf16 WMMA, cp.async pipelined) --------
// block = one (t, 128-tag chunk): tile 256(b) x 128(tags), K = 1024, KT = 64,
// 2-stage cp.async double buffer. b_tag cancels in batch-axis log_softmax.
#define A_STG (256 * 72)     // halves per A stage (ld = 72)
#define B_STG (64 * 136)     // halves per B stage (ld = 136)
#define TAG_SMEM (256 * 136 * 4 + 512 * 4)   // epilogue tile dominates (aliases)

__global__ __launch_bounds__(512, 1) void tag_kernel(float* __restrict__ out) {
    extern __shared__ char smraw[];
    __nv_bfloat16* Asm = (__nv_bfloat16*)smraw;   // 2 stages 256x72
    __nv_bfloat16* Bsm = Asm + 2 * A_STG;         // 2 stages 64x136
    float* Osm = (float*)smraw;                   // 256 x 136 fp32 (alias)
    float* red = Osm + 256 * 136;

    const int tid = threadIdx.x;
    const int t   = blockIdx.y;
    const int c0  = blockIdx.x * 128;
    const int w   = tid >> 5;
    const int wy  = w >> 2;
    const int wx  = w & 3;

    wmma::fragment<wmma::accumulator, 16, 16, 16, float> acc[4][2];
    #pragma unroll
    for (int i = 0; i < 4; i++)
        #pragma unroll
        for (int j = 0; j < 2; j++) wmma::fill_fragment(acc[i][j], 0.f);

    auto issue_tile = [&](int kt) {
        int s  = kt & 1;
        int k0 = kt * 64;
        __nv_bfloat16* As = Asm + s * A_STG;
        __nv_bfloat16* Bs = Bsm + s * B_STG;
        #pragma unroll
        for (int i = 0; i < 4; i++) {
            int e = tid + i * 512;
            int row = e >> 3, c8 = (e & 7) * 8;
            cp16(&As[row * 72 + c8],
                 &g_lstm[((size_t)t * B_ + row) * H_ + k0 + c8]);
        }
        #pragma unroll
        for (int i = 0; i < 2; i++) {
            int e = tid + i * 512;
            int row = e >> 4, c8 = (e & 15) * 8;
            cp16(&Bs[row * 136 + c8],
                 &g_wtag[(size_t)(k0 + row) * TAGS_ + c0 + c8]);
        }
        asm volatile("cp.async.commit_group;\n" ::);
    };

    issue_tile(0);
    for (int kt = 0; kt < 16; kt++) {
        if (kt + 1 < 16) {
            issue_tile(kt + 1);
            asm volatile("cp.async.wait_group 1;\n" ::);
        } else {
            asm volatile("cp.async.wait_group 0;\n" ::);
        }
        __syncthreads();
        int s = kt & 1;
        const __nv_bfloat16* As = Asm + s * A_STG;
        const __nv_bfloat16* Bs = Bsm + s * B_STG;
        #pragma unroll
        for (int ks = 0; ks < 64; ks += 16) {
            wmma::fragment<wmma::matrix_a, 16, 16, 16, __nv_bfloat16, wmma::row_major> af[4];
            wmma::fragment<wmma::matrix_b, 16, 16, 16, __nv_bfloat16, wmma::row_major> bf[2];
            #pragma unroll
            for (int i = 0; i < 4; i++)
                wmma::load_matrix_sync(af[i], &As[(wy * 64 + i * 16) * 72 + ks], 72);
            #pragma unroll
            for (int j = 0; j < 2; j++)
                wmma::load_matrix_sync(bf[j], &Bs[ks * 136 + wx * 32 + j * 16], 136);
            #pragma unroll
            for (int i = 0; i < 4; i++)
                #pragma unroll
                for (int j = 0; j < 2; j++)
                    wmma::mma_sync(acc[i][j], af[i], bf[j], acc[i][j]);
        }
        __syncthreads();
    }

    // spill accumulators to smem tile (aliases stage buffers; final sync above)
    #pragma unroll
    for (int i = 0; i < 4; i++)
        #pragma unroll
        for (int j = 0; j < 2; j++)
            wmma::store_matrix_sync(&Osm[(wy * 64 + i * 16) * 136 + wx * 32 + j * 16],
                                    acc[i][j], 136, wmma::mem_row_major);
    __syncthreads();

    // log_softmax over the 256 rows (batch) per column (tag)
    const int p = tid >> 7;
    const int c = tid & 127;
    float m = -1e30f;
    #pragma unroll 8
    for (int i = 0; i < 64; i++) m = fmaxf(m, Osm[(p * 64 + i) * 136 + c]);
    red[p * 128 + c] = m;
    __syncthreads();
    float M = fmaxf(fmaxf(red[c], red[128 + c]), fmaxf(red[256 + c], red[384 + c]));
    float ssum = 0.f;
    #pragma unroll 8
    for (int i = 0; i < 64; i++) ssum += __expf(Osm[(p * 64 + i) * 136 + c] - M);
    __syncthreads();
    red[p * 128 + c] = ssum;
    __syncthreads();
    float lse = M + logf(red[c] + red[128 + c] + red[256 + c] + red[384 + c]);
    #pragma unroll 8
    for (int i = 0; i < 64; i++) {
        int b = p * 64 + i;
        out[((size_t)t * B_ + b) * TAGS_ + c0 + c] = Osm[b * 136 + c] - lse;
    }
}

// ---------------- launch -----------------------------------------------------
extern "C" void kernel_launch(void* const* d_in, const int* in_sizes, int n_in,
                              void* d_out, int out_size) {
    const int*   sentence = (const int*)  d_in[0];
    const float* emb      = (const float*)d_in[1];
    const float* Wg       = (const float*)d_in[2];
    const float* bg       = (const float*)d_in[3];
    const float* theta    = (const float*)d_in[4];
    const float* Wp       = (const float*)d_in[5];
    const float* bp       = (const float*)d_in[6];
    const float* W_tag    = (const float*)d_in[7];
    // d_in[8] = b_tag: cancels in log_softmax over batch axis -> unused
    float* out = (float*)d_out;

    cudaFuncSetAttribute(lstm_kernel, cudaFuncAttributeMaxDynamicSharedMemorySize, LSTM_SMEM);
    cudaFuncSetAttribute(tag_kernel,  cudaFuncAttributeMaxDynamicSharedMemorySize, TAG_SMEM);

    wtag_convert<<<(H_ * TAGS_) / 256, 256>>>(W_tag);
    embproj_kernel<<<V_ / 128, 256>>>(emb, Wg);
    lstm_kernel<<<B_ / 2, 1024, LSTM_SMEM>>>(sentence, Wg, bg, theta, Wp, bp);
    dim3 g3(TAGS_ / 128, T_);
    tag_kernel<<<g3, 512, TAG_SMEM>>>(out);
}